// round 4
// baseline (speedup 1.0000x reference)
#include <cuda_runtime.h>
#include <math.h>

// Problem constants
#define DHID 1024
#define BATCH 32
#define TSTEPS 513          // number of GRU steps (U+1)
#define N3 3072             // 3 * DHID
#define HROW_PAD 1032       // padded float stride per batch row in SMEM (1032 % 32 == 8 -> conflict-free, 16B aligned)
#define STEP_SMEM (BATCH * HROW_PAD * 4)   // 132096 bytes

// ---------------- scratch (device globals: no allocation allowed) ----------------
__device__ float g_Eproj[1024 * N3];              // embed @ Wx + bx        (12.6 MB)
__device__ float g_WhT[N3 * DHID];                // Wh transposed [3D, D]  (12.6 MB)
__device__ float g_h[(TSTEPS + 1) * BATCH * DHID]; // hidden states, row s=0 is h0 (67.4 MB)

// ---------------- init: broadcast h0 into g_h[0] ----------------
__global__ void init_h_kernel(const float* __restrict__ h0) {
    int idx = blockIdx.x * blockDim.x + threadIdx.x;   // 32 blocks x 1024 threads = 32768
    g_h[idx] = h0[idx & (DHID - 1)];
}

// ---------------- transpose Wh [D,3D] -> WhT [3D,D] ----------------
__global__ void transpose_wh_kernel(const float* __restrict__ Wh) {
    __shared__ float t[32][33];
    int j = blockIdx.x * 32 + threadIdx.x;   // 0..3071
    int d = blockIdx.y * 32 + threadIdx.y;   // 0..1023
    t[threadIdx.y][threadIdx.x] = Wh[(size_t)d * N3 + j];
    __syncthreads();
    int dd = blockIdx.y * 32 + threadIdx.x;
    int jj = blockIdx.x * 32 + threadIdx.y;
    g_WhT[(size_t)jj * DHID + dd] = t[threadIdx.x][threadIdx.y];
}

// ---------------- generic tiled fp32 GEMM: C = A[M,K] * B[K,N] + bias ----------------
// mode 0: C[row*N+col] (used for Eproj)
// mode 1: row = t*32+b  ->  C[(b*513 + t)*1024 + col] (output projection layout [B,T,D])
// Requires: N % 64 == 0, K % 32 == 0. M guarded.
__global__ __launch_bounds__(256)
void gemm_bias_kernel(const float* __restrict__ A, const float* __restrict__ Bm,
                      const float* __restrict__ bias, float* __restrict__ C,
                      int M, int N, int K, int mode) {
    __shared__ float sA[32][68];   // [BK][BM+4], stored transposed
    __shared__ float sB[32][64];   // [BK][BN]
    int bm = blockIdx.y * 64;
    int bn = blockIdx.x * 64;
    int tid = threadIdx.x;
    int tr = tid >> 4;            // 0..15
    int tc = tid & 15;            // 0..15
    float acc[4][4];
#pragma unroll
    for (int i = 0; i < 4; i++)
#pragma unroll
        for (int j = 0; j < 4; j++) acc[i][j] = 0.f;

    for (int k0 = 0; k0 < K; k0 += 32) {
        // load A tile (64 x 32), coalesced along K
#pragma unroll
        for (int i = tid; i < 64 * 32; i += 256) {
            int r = i >> 5, cc = i & 31;
            int gr = bm + r;
            sA[cc][r] = (gr < M) ? A[(size_t)gr * K + k0 + cc] : 0.f;
        }
        // load B tile (32 x 64), coalesced along N
#pragma unroll
        for (int i = tid; i < 32 * 64; i += 256) {
            int r = i >> 6, cc = i & 63;
            sB[r][cc] = Bm[(size_t)(k0 + r) * N + bn + cc];
        }
        __syncthreads();
#pragma unroll
        for (int kk = 0; kk < 32; kk++) {
            float a0 = sA[kk][tr * 4 + 0];
            float a1 = sA[kk][tr * 4 + 1];
            float a2 = sA[kk][tr * 4 + 2];
            float a3 = sA[kk][tr * 4 + 3];
            float b0 = sB[kk][tc * 4 + 0];
            float b1 = sB[kk][tc * 4 + 1];
            float b2 = sB[kk][tc * 4 + 2];
            float b3 = sB[kk][tc * 4 + 3];
            acc[0][0] += a0 * b0; acc[0][1] += a0 * b1; acc[0][2] += a0 * b2; acc[0][3] += a0 * b3;
            acc[1][0] += a1 * b0; acc[1][1] += a1 * b1; acc[1][2] += a1 * b2; acc[1][3] += a1 * b3;
            acc[2][0] += a2 * b0; acc[2][1] += a2 * b1; acc[2][2] += a2 * b2; acc[2][3] += a2 * b3;
            acc[3][0] += a3 * b0; acc[3][1] += a3 * b1; acc[3][2] += a3 * b2; acc[3][3] += a3 * b3;
        }
        __syncthreads();
    }
#pragma unroll
    for (int i = 0; i < 4; i++) {
        int row = bm + tr * 4 + i;
        if (row >= M) continue;
#pragma unroll
        for (int j = 0; j < 4; j++) {
            int col = bn + tc * 4 + j;
            float v = acc[i][j] + bias[col];
            if (mode == 0) {
                C[(size_t)row * N + col] = v;
            } else {
                int t = row >> 5;
                int b = row & 31;
                C[((size_t)b * 513 + t) * 1024 + col] = v;
            }
        }
    }
}

// ---------------- GRU step epilogue helper ----------------
__device__ __forceinline__ void gru_gate_store(int b, int c, int s,
                                               float hz, float hr, float hq,
                                               const float* __restrict__ bh,
                                               const int* __restrict__ y,
                                               const float* __restrict__ sh) {
    hz += bh[c];
    hr += bh[DHID + c];
    hq += bh[2 * DHID + c];
    int tok = (s == 1) ? 0 : y[b * 512 + (s - 2)];
    const float* ep = g_Eproj + (size_t)tok * N3;
    float z  = 1.f / (1.f + expf(-(ep[c] + hz)));
    float r  = 1.f / (1.f + expf(-(ep[DHID + c] + hr)));
    float hc = tanhf(ep[2 * DHID + c] + r * hq);
    float hold = sh[b * HROW_PAD + c];
    g_h[(size_t)s * (BATCH * DHID) + (size_t)b * DHID + c] = z * hold + (1.f - z) * hc;
}

// ---------------- GRU step: h_s = GRU(h_{s-1}) ----------------
// grid = 128 CTAs (8 hidden cols each), 256 threads (8 warps).
// warp w owns batches [4w, 4w+4) and loops over the CTA's 8 columns;
// lanes split the K=1024 reduction (coalesced LDG.128 on WhT, conflict-free LDS on h).
__global__ __launch_bounds__(256, 1)
void gru_step_kernel(const float* __restrict__ bh, const int* __restrict__ y, int s) {
    extern __shared__ float sh[];
    // stage h_{s-1} (32 x 1024 f32) into padded SMEM
    {
        const float4* src = (const float4*)(g_h + (size_t)(s - 1) * (BATCH * DHID));
        float4* dst = (float4*)sh;
        for (int i = threadIdx.x; i < BATCH * (DHID / 4); i += 256) {
            int b = i >> 8;          // /256
            int c4 = i & 255;
            dst[b * (HROW_PAD / 4) + c4] = src[i];
        }
    }
    __syncthreads();

    int w = threadIdx.x >> 5;       // warp id: batch quad
    int lane = threadIdx.x & 31;
    int bbase = w * 4;
    const float4* hv = (const float4*)sh + bbase * (HROW_PAD / 4);

#pragma unroll 1
    for (int ci = 0; ci < 8; ci++) {
        int c = blockIdx.x * 8 + ci;
        const float4* wz4 = (const float4*)(g_WhT + (size_t)c * DHID);
        const float4* wr4 = (const float4*)(g_WhT + (size_t)(DHID + c) * DHID);
        const float4* wq4 = (const float4*)(g_WhT + (size_t)(2 * DHID + c) * DHID);

        float az0 = 0.f, ar0 = 0.f, ah0 = 0.f;
        float az1 = 0.f, ar1 = 0.f, ah1 = 0.f;
        float az2 = 0.f, ar2 = 0.f, ah2 = 0.f;
        float az3 = 0.f, ar3 = 0.f, ah3 = 0.f;

#pragma unroll
        for (int k = 0; k < 8; k++) {
            int o = k * 32 + lane;           // float4 index within the 256-float4 row
            float4 wzv = wz4[o];
            float4 wrv = wr4[o];
            float4 wqv = wq4[o];
            float4 h0v = hv[o];
            float4 h1v = hv[(HROW_PAD / 4) + o];
            float4 h2v = hv[2 * (HROW_PAD / 4) + o];
            float4 h3v = hv[3 * (HROW_PAD / 4) + o];

            az0 += h0v.x * wzv.x + h0v.y * wzv.y + h0v.z * wzv.z + h0v.w * wzv.w;
            ar0 += h0v.x * wrv.x + h0v.y * wrv.y + h0v.z * wrv.z + h0v.w * wrv.w;
            ah0 += h0v.x * wqv.x + h0v.y * wqv.y + h0v.z * wqv.z + h0v.w * wqv.w;

            az1 += h1v.x * wzv.x + h1v.y * wzv.y + h1v.z * wzv.z + h1v.w * wzv.w;
            ar1 += h1v.x * wrv.x + h1v.y * wrv.y + h1v.z * wrv.z + h1v.w * wrv.w;
            ah1 += h1v.x * wqv.x + h1v.y * wqv.y + h1v.z * wqv.z + h1v.w * wqv.w;

            az2 += h2v.x * wzv.x + h2v.y * wzv.y + h2v.z * wzv.z + h2v.w * wzv.w;
            ar2 += h2v.x * wrv.x + h2v.y * wrv.y + h2v.z * wrv.z + h2v.w * wrv.w;
            ah2 += h2v.x * wqv.x + h2v.y * wqv.y + h2v.z * wqv.z + h2v.w * wqv.w;

            az3 += h3v.x * wzv.x + h3v.y * wzv.y + h3v.z * wzv.z + h3v.w * wzv.w;
            ar3 += h3v.x * wrv.x + h3v.y * wrv.y + h3v.z * wrv.z + h3v.w * wrv.w;
            ah3 += h3v.x * wqv.x + h3v.y * wqv.y + h3v.z * wqv.z + h3v.w * wqv.w;
        }

        // warp reduction (all 12 accumulators)
#pragma unroll
        for (int off = 16; off; off >>= 1) {
            az0 += __shfl_down_sync(0xffffffffu, az0, off);
            ar0 += __shfl_down_sync(0xffffffffu, ar0, off);
            ah0 += __shfl_down_sync(0xffffffffu, ah0, off);
            az1 += __shfl_down_sync(0xffffffffu, az1, off);
            ar1 += __shfl_down_sync(0xffffffffu, ar1, off);
            ah1 += __shfl_down_sync(0xffffffffu, ah1, off);
            az2 += __shfl_down_sync(0xffffffffu, az2, off);
            ar2 += __shfl_down_sync(0xffffffffu, ar2, off);
            ah2 += __shfl_down_sync(0xffffffffu, ah2, off);
            az3 += __shfl_down_sync(0xffffffffu, az3, off);
            ar3 += __shfl_down_sync(0xffffffffu, ar3, off);
            ah3 += __shfl_down_sync(0xffffffffu, ah3, off);
        }

        if (lane == 0) {
            gru_gate_store(bbase + 0, c, s, az0, ar0, ah0, bh, y, sh);
            gru_gate_store(bbase + 1, c, s, az1, ar1, ah1, bh, y, sh);
            gru_gate_store(bbase + 2, c, s, az2, ar2, ah2, bh, y, sh);
            gru_gate_store(bbase + 3, c, s, az3, ar3, ah3, bh, y, sh);
        }
    }
}

// ---------------- launch ----------------
extern "C" void kernel_launch(void* const* d_in, const int* in_sizes, int n_in,
                              void* d_out, int out_size) {
    const int*   y   = (const int*)d_in[0];
    const float* emb = (const float*)d_in[1];
    const float* Wx  = (const float*)d_in[2];
    const float* Wh  = (const float*)d_in[3];
    const float* bx  = (const float*)d_in[4];
    const float* bh  = (const float*)d_in[5];
    const float* Wd  = (const float*)d_in[6];
    const float* bd  = (const float*)d_in[7];
    const float* h0  = (const float*)d_in[8];
    float* out = (float*)d_out;

    float *pE, *pH;
    cudaGetSymbolAddress((void**)&pE, g_Eproj);
    cudaGetSymbolAddress((void**)&pH, g_h);

    cudaFuncSetAttribute(gru_step_kernel,
                         cudaFuncAttributeMaxDynamicSharedMemorySize, STEP_SMEM);

    // h_0 = broadcast(h0)
    init_h_kernel<<<32, 1024>>>(h0);
    // WhT = transpose(Wh)
    transpose_wh_kernel<<<dim3(96, 32), dim3(32, 32)>>>(Wh);
    // Eproj = embed_table @ Wx + bx   (only 1024 distinct token rows!)
    gemm_bias_kernel<<<dim3(48, 16), 256>>>(emb, Wx, bx, pE, 1024, N3, 1024, 0);
    // sequential GRU recurrence
    for (int s = 1; s <= TSTEPS; ++s)
        gru_step_kernel<<<128, 256, STEP_SMEM>>>(bh, y, s);
    // outs[b,t,:] = h_{t+1}[b,:] @ Wd + bd
    gemm_bias_kernel<<<dim3(16, 257), 256>>>(pH + BATCH * DHID, Wd, bd, out,
                                             TSTEPS * BATCH, 1024, 1024, 1);
}

// round 5
// speedup vs baseline: 1.0523x; 1.0523x over previous
#include <cuda_runtime.h>
#include <math.h>

typedef unsigned long long ull;

// Problem constants
#define DHID   1024
#define BATCH  32
#define TSTEPS 513           // GRU steps (U+1)
#define N3     3072
#define NCTA   128           // persistent grid: 8 hidden units per CTA
#define STEP_SMEM (BATCH * DHID * 4)   // 131072 bytes: h in [k4][b][4] packed layout

// ---------------- f32x2 packed-FMA helpers ----------------
#define FMA2(acc, a, b) asm("fma.rn.f32x2 %0, %1, %2, %0;" : "+l"(acc) : "l"(a), "l"(b))
#define PACKDUP(d, v)   asm("mov.b64 %0, {%1, %1};" : "=l"(d) : "f"(v))
#define UNPK(lo, hi, v) asm("mov.b64 {%0, %1}, %2;" : "=f"(lo), "=f"(hi) : "l"(v))

// ---------------- device scratch (no allocation allowed) ----------------
__device__ float g_Eproj[1024 * N3];                       // embed @ Wx + bx (12.6 MB)
__device__ uint4 g_WhT4[(size_t)N3 * (DHID / 4)];          // Wh^T [3D][D], 16B aligned
__device__ uint4 g_hp4[(size_t)(TSTEPS + 1) * (BATCH * DHID / 4)];  // h packed [s][k4][b][4]
__device__ float g_hf[(size_t)(TSTEPS + 1) * BATCH * DHID];         // h flat   [s][b][k]
__device__ unsigned g_cnt[TSTEPS + 2];                     // per-step barrier counters

// ---------------- init: packed h0 broadcast + barrier counter reset ----------------
__global__ void init_kernel(const float* __restrict__ h0) {
    int idx = blockIdx.x * blockDim.x + threadIdx.x;       // 32768 threads
    // packed layout idx = (k4*32 + b)*4 + kj  ->  k = 4*k4 + kj
    int k = ((idx >> 7) << 2) | (idx & 3);
    ((float*)g_hp4)[idx] = h0[k];
    if (idx < TSTEPS + 2) g_cnt[idx] = 0;
}

// ---------------- transpose Wh [D,3D] -> WhT [3D,D] ----------------
__global__ void transpose_wh_kernel(const float* __restrict__ Wh) {
    __shared__ float t[32][33];
    int j = blockIdx.x * 32 + threadIdx.x;   // 0..3071
    int d = blockIdx.y * 32 + threadIdx.y;   // 0..1023
    t[threadIdx.y][threadIdx.x] = Wh[(size_t)d * N3 + j];
    __syncthreads();
    int dd = blockIdx.y * 32 + threadIdx.x;
    int jj = blockIdx.x * 32 + threadIdx.y;
    ((float*)g_WhT4)[(size_t)jj * DHID + dd] = t[threadIdx.x][threadIdx.y];
}

// ---------------- packed-fp32 tiled GEMM: C = A[M,K]*B[K,N] + bias ----------------
// mode 0: C[row*N+col]
// mode 1: row = t*32+b -> C[(b*513+t)*1024+col]   (output layout [B,T,D])
__global__ __launch_bounds__(256)
void gemm_bias_kernel(const float* __restrict__ A, const float* __restrict__ Bm,
                      const float* __restrict__ bias, float* __restrict__ C,
                      int M, int N, int K, int mode) {
    __shared__ ull   sAd[32][65];  // A tile dup-packed {a,a}; pad 65 -> STS.64 conflict-light
    __shared__ float sB[32][64];
    int bm = blockIdx.y * 64, bn = blockIdx.x * 64;
    int tid = threadIdx.x;
    int tr = tid >> 4, tc = tid & 15;
    ull acc[4][2];
#pragma unroll
    for (int i = 0; i < 4; i++) { acc[i][0] = 0ull; acc[i][1] = 0ull; }

    for (int k0 = 0; k0 < K; k0 += 32) {
#pragma unroll
        for (int i = tid; i < 64 * 32; i += 256) {
            int r = i >> 5, cc = i & 31;
            int gr = bm + r;
            float v = (gr < M) ? A[(size_t)gr * K + k0 + cc] : 0.f;
            ull dv; PACKDUP(dv, v);
            sAd[cc][r] = dv;
        }
#pragma unroll
        for (int i = tid; i < 32 * 64; i += 256) {
            int r = i >> 6, cc = i & 63;
            sB[r][cc] = Bm[(size_t)(k0 + r) * N + bn + cc];
        }
        __syncthreads();
#pragma unroll
        for (int kk = 0; kk < 32; kk++) {
            ull a0 = sAd[kk][tr * 4 + 0];
            ull a1 = sAd[kk][tr * 4 + 1];
            ull a2 = sAd[kk][tr * 4 + 2];
            ull a3 = sAd[kk][tr * 4 + 3];
            ull b0 = *(const ull*)&sB[kk][tc * 4];
            ull b1 = *(const ull*)&sB[kk][tc * 4 + 2];
            FMA2(acc[0][0], a0, b0); FMA2(acc[0][1], a0, b1);
            FMA2(acc[1][0], a1, b0); FMA2(acc[1][1], a1, b1);
            FMA2(acc[2][0], a2, b0); FMA2(acc[2][1], a2, b1);
            FMA2(acc[3][0], a3, b0); FMA2(acc[3][1], a3, b1);
        }
        __syncthreads();
    }
#pragma unroll
    for (int i = 0; i < 4; i++) {
        int row = bm + tr * 4 + i;
        if (row >= M) continue;
#pragma unroll
        for (int j2 = 0; j2 < 2; j2++) {
            float lo, hi; UNPK(lo, hi, acc[i][j2]);
            int c0 = bn + tc * 4 + 2 * j2;
            float v0 = lo + bias[c0];
            float v1 = hi + bias[c0 + 1];
            if (mode == 0) {
                C[(size_t)row * N + c0]     = v0;
                C[(size_t)row * N + c0 + 1] = v1;
            } else {
                int t = row >> 5, b = row & 31;
                size_t o = ((size_t)b * 513 + t) * 1024 + c0;
                C[o]     = v0;
                C[o + 1] = v1;
            }
        }
    }
}

// ---------------- persistent GRU recurrence ----------------
// 128 CTAs x 256 threads (all resident: 1 CTA/SM). Warp = one hidden unit j.
// Lanes = 32 batches. Per step: stage packed h into SMEM, 256x {3 LDG.128 (Wh,
// L1-hot across steps) + 1 LDS.128 (h) + 6 FFMA2}, all-lane gate epilogue,
// dual store (packed for next-step staging, flat for the output GEMM),
// then a grid-wide sense barrier (per-step counters, reset each launch).
__global__ __launch_bounds__(256, 1)
void gru_persist_kernel(const float* __restrict__ bh, const int* __restrict__ y) {
    extern __shared__ uint4 sh4[];   // 8192 x 16B = h [k4][b][4]
    const int tid  = threadIdx.x;
    const int lane = tid & 31;
    const int w    = tid >> 5;
    const int j    = blockIdx.x * 8 + w;          // hidden unit 0..1023

    const ulonglong2* wz = (const ulonglong2*)(g_WhT4 + (size_t)j * 256);
    const ulonglong2* wr = (const ulonglong2*)(g_WhT4 + (size_t)(1024 + j) * 256);
    const ulonglong2* wq = (const ulonglong2*)(g_WhT4 + (size_t)(2048 + j) * 256);
    const float bz = bh[j], br = bh[DHID + j], bq = bh[2 * DHID + j];
    const int hidx = ((j >> 2) * 32 + lane) * 4 + (j & 3);   // packed offset of h[b=lane][j]

    for (int s = 1; s <= TSTEPS; ++s) {
        // stage packed h_{s-1}: pure 128KB memcpy, L1-bypass (keep Wh resident)
        const uint4* src = g_hp4 + (size_t)(s - 1) * 8192;
#pragma unroll
        for (int i = 0; i < 32; i++)
            sh4[tid + i * 256] = __ldcg(&src[tid + i * 256]);
        __syncthreads();

        ull az0 = 0, az1 = 0, ar0 = 0, ar1 = 0, aq0 = 0, aq1 = 0;
        const ulonglong2* hp = (const ulonglong2*)sh4 + lane;
#pragma unroll 4
        for (int k4 = 0; k4 < 256; k4++) {
            ulonglong2 hv = hp[k4 * 32];
            ulonglong2 z2 = wz[k4];
            ulonglong2 r2 = wr[k4];
            ulonglong2 q2 = wq[k4];
            FMA2(az0, z2.x, hv.x); FMA2(az1, z2.y, hv.y);
            FMA2(ar0, r2.x, hv.x); FMA2(ar1, r2.y, hv.y);
            FMA2(aq0, q2.x, hv.x); FMA2(aq1, q2.y, hv.y);
        }
        float l0, h0_, l1, h1_;
        UNPK(l0, h0_, az0); UNPK(l1, h1_, az1);
        float hz = (l0 + l1) + (h0_ + h1_) + bz;
        UNPK(l0, h0_, ar0); UNPK(l1, h1_, ar1);
        float hr = (l0 + l1) + (h0_ + h1_) + br;
        UNPK(l0, h0_, aq0); UNPK(l1, h1_, aq1);
        float hq = (l0 + l1) + (h0_ + h1_) + bq;

        // gates: lane = batch, fully parallel epilogue
        int tok = (s == 1) ? 0 : __ldg(&y[lane * 512 + (s - 2)]);
        const float* ep = g_Eproj + (size_t)tok * N3;
        float ez = __ldg(&ep[j]);
        float er = __ldg(&ep[DHID + j]);
        float eq = __ldg(&ep[2 * DHID + j]);
        float zg = 1.f / (1.f + expf(-(ez + hz)));
        float rg = 1.f / (1.f + expf(-(er + hr)));
        float hc = tanhf(eq + rg * hq);
        float hold = ((const float*)sh4)[hidx];
        float hn = zg * hold + (1.f - zg) * hc;

        ((float*)g_hp4)[(size_t)s * 32768 + hidx] = hn;             // packed (next step)
        g_hf[(size_t)s * 32768 + (size_t)lane * 1024 + j] = hn;     // flat (output GEMM)

        // grid barrier (all 128 CTAs resident; fresh counter per step)
        __syncthreads();
        if (tid == 0) {
            __threadfence();
            atomicAdd(&g_cnt[s], 1u);
            while (((volatile unsigned*)g_cnt)[s] < (unsigned)NCTA) { }
        }
        __syncthreads();
    }
}

// ---------------- launch ----------------
extern "C" void kernel_launch(void* const* d_in, const int* in_sizes, int n_in,
                              void* d_out, int out_size) {
    const int*   y   = (const int*)d_in[0];
    const float* emb = (const float*)d_in[1];
    const float* Wx  = (const float*)d_in[2];
    const float* Wh  = (const float*)d_in[3];
    const float* bx  = (const float*)d_in[4];
    const float* bh  = (const float*)d_in[5];
    const float* Wd  = (const float*)d_in[6];
    const float* bd  = (const float*)d_in[7];
    const float* h0  = (const float*)d_in[8];
    float* out = (float*)d_out;

    float *pE, *pHf;
    cudaGetSymbolAddress((void**)&pE, g_Eproj);
    cudaGetSymbolAddress((void**)&pHf, g_hf);

    cudaFuncSetAttribute(gru_persist_kernel,
                         cudaFuncAttributeMaxDynamicSharedMemorySize, STEP_SMEM);

    // init packed h0 + reset barrier counters (every replay)
    init_kernel<<<32, 1024>>>(h0);
    // WhT = transpose(Wh)
    transpose_wh_kernel<<<dim3(96, 32), dim3(32, 32)>>>(Wh);
    // Eproj = embed_table @ Wx + bx (only 1024 distinct token rows)
    gemm_bias_kernel<<<dim3(48, 16), 256>>>(emb, Wx, bx, pE, 1024, N3, 1024, 0);
    // persistent GRU recurrence (513 steps, one launch)
    gru_persist_kernel<<<NCTA, 256, STEP_SMEM>>>(bh, y);
    // outs[b,t,:] = h_{t+1}[b,:] @ Wd + bd   (g_hf is row-major [16416,1024] from s=1)
    gemm_bias_kernel<<<dim3(16, 257), 256>>>(pHf + 32768, Wd, bd, out,
                                             TSTEPS * BATCH, 1024, 1024, 1);
}

// round 6
// speedup vs baseline: 2.1193x; 2.0140x over previous
#include <cuda_runtime.h>
#include <math.h>

typedef unsigned long long ull;

// Problem constants
#define DHID   1024
#define BATCH  32
#define TSTEPS 513           // GRU steps (U+1)
#define N3     3072
#define NCTA   128           // persistent grid: 8 hidden units per CTA, 1 CTA/SM

// SMEM: Wh slice [24 rows][1024] (96KB) + exchange [8 warps][24 rows][32 b] (24KB)
#define WH_SM_FLOATS (24 * 1024)
#define EXCH_FLOATS  (8 * 24 * 32)
#define STEP_SMEM    ((WH_SM_FLOATS + EXCH_FLOATS) * 4)   // 122880 bytes

// ---------------- f32x2 packed-FMA helpers ----------------
#define FMA2(acc, a, b) asm("fma.rn.f32x2 %0, %1, %2, %0;" : "+l"(acc) : "l"(a), "l"(b))
#define PACKDUP(d, v)   asm("mov.b64 %0, {%1, %1};" : "=l"(d) : "f"(v))
#define UNPK(lo, hi, v) asm("mov.b64 {%0, %1}, %2;" : "=f"(lo), "=f"(hi) : "l"(v))

// ---------------- device scratch (no allocation allowed) ----------------
__device__ float g_Eproj[1024 * N3];                       // embed @ Wx + bx (12.6 MB)
__device__ uint4 g_WhT4[(size_t)N3 * (DHID / 4)];          // Wh^T [3D][D], 16B aligned
__device__ uint4 g_hp4[(size_t)(TSTEPS + 1) * (BATCH * DHID / 4)];  // h packed [s][k4][b][4]
__device__ float g_hf[(size_t)(TSTEPS + 1) * BATCH * DHID];         // h flat   [s][b][k]
__device__ unsigned g_cnt[TSTEPS + 2];                     // per-step barrier counters

// ---------------- init: packed h0 broadcast + barrier counter reset ----------------
__global__ void init_kernel(const float* __restrict__ h0) {
    int idx = blockIdx.x * blockDim.x + threadIdx.x;       // 32768 threads
    int k = ((idx >> 7) << 2) | (idx & 3);                 // packed [k4][b][4]
    ((float*)g_hp4)[idx] = h0[k];
    if (idx < TSTEPS + 2) g_cnt[idx] = 0;
}

// ---------------- transpose Wh [D,3D] -> WhT [3D,D] ----------------
__global__ void transpose_wh_kernel(const float* __restrict__ Wh) {
    __shared__ float t[32][33];
    int j = blockIdx.x * 32 + threadIdx.x;
    int d = blockIdx.y * 32 + threadIdx.y;
    t[threadIdx.y][threadIdx.x] = Wh[(size_t)d * N3 + j];
    __syncthreads();
    int dd = blockIdx.y * 32 + threadIdx.x;
    int jj = blockIdx.x * 32 + threadIdx.y;
    ((float*)g_WhT4)[(size_t)jj * DHID + dd] = t[threadIdx.x][threadIdx.y];
}

// ---------------- packed-fp32 tiled GEMM: C = A[M,K]*B[K,N] + bias ----------------
// mode 0: C[row*N+col]   mode 1: row=t*32+b -> C[(b*513+t)*1024+col]
__global__ __launch_bounds__(256)
void gemm_bias_kernel(const float* __restrict__ A, const float* __restrict__ Bm,
                      const float* __restrict__ bias, float* __restrict__ C,
                      int M, int N, int K, int mode) {
    __shared__ ull   sAd[32][65];
    __shared__ float sB[32][64];
    int bm = blockIdx.y * 64, bn = blockIdx.x * 64;
    int tid = threadIdx.x;
    int tr = tid >> 4, tc = tid & 15;
    ull acc[4][2];
#pragma unroll
    for (int i = 0; i < 4; i++) { acc[i][0] = 0ull; acc[i][1] = 0ull; }

    for (int k0 = 0; k0 < K; k0 += 32) {
#pragma unroll
        for (int i = tid; i < 64 * 32; i += 256) {
            int r = i >> 5, cc = i & 31;
            int gr = bm + r;
            float v = (gr < M) ? A[(size_t)gr * K + k0 + cc] : 0.f;
            ull dv; PACKDUP(dv, v);
            sAd[cc][r] = dv;
        }
#pragma unroll
        for (int i = tid; i < 32 * 64; i += 256) {
            int r = i >> 6, cc = i & 63;
            sB[r][cc] = Bm[(size_t)(k0 + r) * N + bn + cc];
        }
        __syncthreads();
#pragma unroll
        for (int kk = 0; kk < 32; kk++) {
            ull a0 = sAd[kk][tr * 4 + 0];
            ull a1 = sAd[kk][tr * 4 + 1];
            ull a2 = sAd[kk][tr * 4 + 2];
            ull a3 = sAd[kk][tr * 4 + 3];
            ull b0 = *(const ull*)&sB[kk][tc * 4];
            ull b1 = *(const ull*)&sB[kk][tc * 4 + 2];
            FMA2(acc[0][0], a0, b0); FMA2(acc[0][1], a0, b1);
            FMA2(acc[1][0], a1, b0); FMA2(acc[1][1], a1, b1);
            FMA2(acc[2][0], a2, b0); FMA2(acc[2][1], a2, b1);
            FMA2(acc[3][0], a3, b0); FMA2(acc[3][1], a3, b1);
        }
        __syncthreads();
    }
#pragma unroll
    for (int i = 0; i < 4; i++) {
        int row = bm + tr * 4 + i;
        if (row >= M) continue;
#pragma unroll
        for (int j2 = 0; j2 < 2; j2++) {
            float lo, hi; UNPK(lo, hi, acc[i][j2]);
            int c0 = bn + tc * 4 + 2 * j2;
            float v0 = lo + bias[c0];
            float v1 = hi + bias[c0 + 1];
            if (mode == 0) {
                C[(size_t)row * N + c0]     = v0;
                C[(size_t)row * N + c0 + 1] = v1;
            } else {
                int t = row >> 5, b = row & 31;
                size_t o = ((size_t)b * 513 + t) * 1024 + c0;
                C[o]     = v0;
                C[o + 1] = v1;
            }
        }
    }
}

// ---------------- persistent GRU recurrence ----------------
// 128 CTAs x 256 threads (1/SM). CTA owns units j = bid*8..bid*8+7.
// Wh slice (24 rows x 1024) lives in SMEM for the whole launch.
// Per step: warp w reduces k-slice [w*128, w*128+128) for ALL 24 rows x 32
// batches (lane=batch): per k4 -> 1 LDG.128 of h (L2, .cg) + 24 uniform 16B
// LDS of Wh + 48 FFMA2. 8 partials exchanged via SMEM; 256-thread epilogue
// (thread = (unit,batch)) applies gates; grid-wide sense barrier per step.
__global__ __launch_bounds__(256, 1)
void gru_persist_kernel(const float* __restrict__ bh, const int* __restrict__ y) {
    extern __shared__ float sm[];
    float* swh = sm;                       // [24][1024]
    float* sex = sm + WH_SM_FLOATS;        // [8 warps][24 rows][32 b]

    const int tid  = threadIdx.x;
    const int lane = tid & 31;
    const int w    = tid >> 5;
    const int jbase = blockIdx.x * 8;

    // one-time: load Wh slice into SMEM (row r = u*3+g <- WhT row g*1024+jbase+u)
    for (int i = tid; i < 24 * 256; i += 256) {
        int r = i >> 8, c = i & 255;
        int u = r / 3, g = r - 3 * u;
        ((uint4*)swh)[r * 256 + c] = g_WhT4[(size_t)(g * 1024 + jbase + u) * 256 + c];
    }
    // epilogue constants for this thread: (unit u=w, batch b=lane)
    const int j = jbase + w;
    const float bz = bh[j], br = bh[DHID + j], bq = bh[2 * DHID + j];
    const int holdoff = ((j >> 2) * 32 + lane) * 4 + (j & 3);  // packed idx of h[b][j]
    __syncthreads();

    for (int s = 1; s <= TSTEPS; ++s) {
        const size_t sbase = (size_t)(s - 1) * 8192;

        // prefetch epilogue inputs early (hidden under the FMA loop)
        int tok = (s == 1) ? 0 : __ldg(&y[lane * 512 + (s - 2)]);
        const float* ep = g_Eproj + (size_t)tok * N3;
        float ez = __ldg(ep + j);
        float er = __ldg(ep + DHID + j);
        float eq = __ldg(ep + 2 * DHID + j);
        float hold = __ldcg(((const float*)g_hp4) + (sbase << 2) + holdoff);

        // ---- main reduction: warp's 32 k4-chunks, 24 rows, lane = batch ----
        ull acc[24];
#pragma unroll
        for (int r = 0; r < 24; r++) acc[r] = 0ull;

        const ulonglong2* hp = ((const ulonglong2*)g_hp4) + sbase + (size_t)(w * 32) * 32 + lane;
        const float* wb0 = swh + (w * 32) * 4;

        ulonglong2 h0v = __ldcg(hp);
        ulonglong2 h1v = __ldcg(hp + 32);
#pragma unroll 4
        for (int kk = 0; kk < 32; kk++) {
            // depth-2 prefetch (reads past the slice land inside g_hp4; unused)
            ulonglong2 h2v = __ldcg(hp + (kk + 2) * 32);
            const float* wb = wb0 + kk * 4;
#pragma unroll
            for (int r = 0; r < 24; r++) {
                ulonglong2 wv = *(const ulonglong2*)(wb + r * 1024);
                FMA2(acc[r], wv.x, h0v.x);
                FMA2(acc[r], wv.y, h0v.y);
            }
            h0v = h1v; h1v = h2v;
        }

        // fold f32x2 and publish partials: sex[w][r][lane]
#pragma unroll
        for (int r = 0; r < 24; r++) {
            float lo, hi; UNPK(lo, hi, acc[r]);
            sex[(w * 24 + r) * 32 + lane] = lo + hi;
        }
        __syncthreads();

        // ---- epilogue: thread (u=w, b=lane) ----
        float hz = bz, hr = br, hq = bq;
#pragma unroll
        for (int w2 = 0; w2 < 8; w2++) {
            hz += sex[(w2 * 24 + w * 3 + 0) * 32 + lane];
            hr += sex[(w2 * 24 + w * 3 + 1) * 32 + lane];
            hq += sex[(w2 * 24 + w * 3 + 2) * 32 + lane];
        }
        float zg = __fdividef(1.f, 1.f + __expf(-(ez + hz)));
        float rg = __fdividef(1.f, 1.f + __expf(-(er + hr)));
        float xq = eq + rg * hq;
        float e2 = __expf(2.f * xq);
        float hc = 1.f - __fdividef(2.f, e2 + 1.f);
        float hn = zg * hold + (1.f - zg) * hc;

        ((float*)g_hp4)[((sbase + 8192) << 2) + holdoff] = hn;         // packed (next step)
        g_hf[(size_t)s * 32768 + (size_t)lane * 1024 + j] = hn;        // flat (output GEMM)

        // ---- grid barrier (all 128 CTAs resident; fresh counter per step) ----
        __syncthreads();
        if (s < TSTEPS) {
            if (tid == 0) {
                __threadfence();
                atomicAdd(&g_cnt[s], 1u);
                while (((volatile unsigned*)g_cnt)[s] < (unsigned)NCTA) { }
            }
            __syncthreads();
        }
    }
}

// ---------------- launch ----------------
extern "C" void kernel_launch(void* const* d_in, const int* in_sizes, int n_in,
                              void* d_out, int out_size) {
    const int*   y   = (const int*)d_in[0];
    const float* emb = (const float*)d_in[1];
    const float* Wx  = (const float*)d_in[2];
    const float* Wh  = (const float*)d_in[3];
    const float* bx  = (const float*)d_in[4];
    const float* bh  = (const float*)d_in[5];
    const float* Wd  = (const float*)d_in[6];
    const float* bd  = (const float*)d_in[7];
    const float* h0  = (const float*)d_in[8];
    float* out = (float*)d_out;

    float *pE, *pHf;
    cudaGetSymbolAddress((void**)&pE, g_Eproj);
    cudaGetSymbolAddress((void**)&pHf, g_hf);

    cudaFuncSetAttribute(gru_persist_kernel,
                         cudaFuncAttributeMaxDynamicSharedMemorySize, STEP_SMEM);

    // init packed h0 + reset barrier counters (every replay)
    init_kernel<<<32, 1024>>>(h0);
    // WhT = transpose(Wh)
    transpose_wh_kernel<<<dim3(96, 32), dim3(32, 32)>>>(Wh);
    // Eproj = embed_table @ Wx + bx (only 1024 distinct token rows)
    gemm_bias_kernel<<<dim3(48, 16), 256>>>(emb, Wx, bx, pE, 1024, N3, 1024, 0);
    // persistent GRU recurrence (513 steps, one launch)
    gru_persist_kernel<<<NCTA, 256, STEP_SMEM>>>(bh, y);
    // outs[b,t,:] = h_{t+1}[b,:] @ Wd + bd
    gemm_bias_kernel<<<dim3(16, 257), 256>>>(pHf + 32768, Wd, bd, out,
                                             TSTEPS * BATCH, 1024, 1024, 1);
}